// round 4
// baseline (speedup 1.0000x reference)
#include <cuda_runtime.h>

// ---------------------------------------------------------------------------
// ftat_BiLSTM — 4-kernel split, round 4 (round-3 design, dot64_pk index fix):
//  K1 feature attention   (2048 x 128t)            -> g_fa
//  K2 BiLSTM H=64 split-K (grid (2048,2) x 512t)   -> g_lof/g_lob
//  K3 temporal attn + LSTM2-input GEMM (2048x512t) -> g_xg
//  K4 LSTM2 recurrence + FC, warp-per-batch        -> out   (no barriers)
// ---------------------------------------------------------------------------

namespace {
constexpr int Bn = 2048, Sn = 96, Dn = 7, Hn = 64;
using u64 = unsigned long long;
} // namespace

__device__ float g_fa [Bn * Sn * 8];    // fa, padded stride 8
__device__ float g_lof[Bn * Sn * Hn];   // 0.5*hf
__device__ float g_lob[Bn * Sn * Hn];   // 0.5*hb
__device__ float g_xg [Bn * Sn * Hn];   // LSTM2 input gates (pre-activation)

__device__ __forceinline__ float sigf(float x) { return 1.0f / (1.0f + __expf(-x)); }
__device__ __forceinline__ float tanhfast(float x) { return 1.0f - 2.0f / (__expf(2.0f * x) + 1.0f); }

__device__ __forceinline__ u64 ffma2(u64 a, u64 b, u64 c) {
    u64 d; asm("fma.rn.f32x2 %0, %1, %2, %3;" : "=l"(d) : "l"(a), "l"(b), "l"(c)); return d;
}
__device__ __forceinline__ float2 unpack2(u64 v) {
    float2 r; asm("mov.b64 {%0, %1}, %2;" : "=f"(r.x), "=f"(r.y) : "l"(v)); return r;
}
__device__ __forceinline__ u64 pack2(float lo, float hi) {
    u64 v; asm("mov.b64 %0, {%1, %2};" : "=l"(v) : "f"(lo), "f"(hi)); return v;
}
__device__ __forceinline__ u64 dup2(float x) {
    u64 v; asm("mov.b64 %0, {%1, %1};" : "=l"(v) : "f"(x)); return v;
}

// packed dot over 64 floats: x via float4 loads, w as 32 packed u64.
// u64 w[k] covers floats (2k, 2k+1)  =>  float4 x4[j] (floats 4j..4j+3)
// pairs with w[2j] and w[2j+1].   (round-3 bug: used w[4j].)
__device__ __forceinline__ float dot64_pk(const float* __restrict__ x, const u64* __restrict__ w) {
    u64 a0 = 0ull, a1 = 0ull, a2 = 0ull, a3 = 0ull;
    const float4* x4 = (const float4*)x;
#pragma unroll
    for (int j = 0; j < 16; j += 2) {
        float4 v0 = x4[j], v1 = x4[j + 1];
        a0 = ffma2(pack2(v0.x, v0.y), w[2 * j + 0], a0);
        a1 = ffma2(pack2(v0.z, v0.w), w[2 * j + 1], a1);
        a2 = ffma2(pack2(v1.x, v1.y), w[2 * j + 2], a2);
        a3 = ffma2(pack2(v1.z, v1.w), w[2 * j + 3], a3);
    }
    float2 f0 = unpack2(a0), f1 = unpack2(a1), f2 = unpack2(a2), f3 = unpack2(a3);
    return ((f0.x + f0.y) + (f1.x + f1.y)) + ((f2.x + f2.y) + (f3.x + f3.y));
}

// =========================== K1: feature attention ===========================
struct P1 { const float *x, *fv_w, *fv_b, *fk_w, *fk_b, *fq_w, *fq_b; };

__global__ void __launch_bounds__(128) k1_featatt(P1 P) {
    __shared__ __align__(16) float sFA[Sn * 8];
    __shared__ __align__(16) float sV[Sn * 8];
    __shared__ __align__(16) float sK[Sn * 8];
    __shared__ __align__(16) float sQ[Sn * 8];
    __shared__ float sATT[7 * 8];
    const int b = blockIdx.x, t = threadIdx.x;
    const float* x = P.x + (size_t)b * (Sn * Dn);
    for (int idx = t; idx < Sn * Dn; idx += 128) {
        int s = idx / 7, j = idx - s * 7;
        sFA[s * 8 + j] = x[idx];
    }
    if (t < Sn) sFA[t * 8 + 7] = 0.0f;
    __syncthreads();
    for (int idx = t; idx < Sn * Dn; idx += 128) {
        int s = idx / 7, i = idx - s * 7;
        float a = P.fv_b[i];
#pragma unroll
        for (int j = 0; j < 7; j++) a += sFA[s * 8 + j] * P.fv_w[i * 7 + j];
        sV[s * 8 + i] = a;
    }
    __syncthreads();
    for (int idx = t; idx < Sn * Dn; idx += 128) {
        int s = idx / 7, i = idx - s * 7;
        float a = P.fk_b[i];
#pragma unroll
        for (int j = 0; j < 7; j++) a += (sFA[s * 8 + j] + sV[s * 8 + j]) * P.fk_w[i * 7 + j];
        sK[s * 8 + i] = a;
    }
    __syncthreads();
    for (int idx = t; idx < Sn * Dn; idx += 128) {
        int s = idx / 7, i = idx - s * 7;
        float a = P.fq_b[i];
#pragma unroll
        for (int j = 0; j < 7; j++) a += (sFA[s * 8 + j] + sK[s * 8 + j]) * P.fq_w[i * 7 + j];
        sQ[s * 8 + i] = a;
    }
    __syncthreads();
    if (t < 49) {
        int i = t / 7, j = t - (t / 7) * 7;
        float a = 0.0f;
        for (int s = 0; s < Sn; s++) a += sQ[s * 8 + i] * sK[s * 8 + j];
        sATT[i * 8 + j] = a;
    }
    __syncthreads();
    if (t < 7) {
        float* row = sATT + t * 8;
        float m = row[0];
#pragma unroll
        for (int j = 1; j < 7; j++) m = fmaxf(m, row[j]);
        float ssum = 0.0f;
#pragma unroll
        for (int j = 0; j < 7; j++) { float e = __expf(row[j] - m); row[j] = e; ssum += e; }
        float inv = 1.0f / ssum;
#pragma unroll
        for (int j = 0; j < 7; j++) row[j] *= inv;
    }
    __syncthreads();
    for (int idx = t; idx < Sn * Dn; idx += 128) {
        int s = idx / 7, j = idx - s * 7;
        float a = sFA[s * 8 + j];
#pragma unroll
        for (int i = 0; i < 7; i++) a += sV[s * 8 + i] * sATT[i * 8 + j];
        sFA[s * 8 + j] = tanhfast(a);
    }
    __syncthreads();
    float* fa = g_fa + (size_t)b * (Sn * 8);
    for (int idx = t; idx < Sn * 8; idx += 128) fa[idx] = sFA[idx];
}

// =========================== K2: BiLSTM, split-K gates ===========================
struct P2 {
    const float *l1f_wih, *l1f_whh, *l1f_bih, *l1f_bhh;
    const float *l1b_wih, *l1b_whh, *l1b_bih, *l1b_bhh;
};

__global__ void __launch_bounds__(512, 2) k2_bilstm(P2 P) {
    __shared__ __align__(16) float sFA[Sn * 8];
    __shared__ __align__(16) float sWST[64 * 68];
    __shared__ __align__(16) float sH[Hn];
    __shared__ float sG[256];
    const int b = blockIdx.x, dir = blockIdx.y, t = threadIdx.x;
    const int p = t >> 1;      // gate index 0..255
    const int hh = t & 1;      // which 32-wide half of the h-dot

    {
        const float* fa = g_fa + (size_t)b * (Sn * 8);
        for (int idx = t; idx < Sn * 8; idx += 512) sFA[idx] = fa[idx];
    }
    // stage whh, 4 rounds of 64 rows; thread grabs its half-row (16 u64)
    const float* whh = dir ? P.l1b_whh : P.l1f_whh;
    u64 wpk[16];
#pragma unroll 1
    for (int r = 0; r < 4; r++) {
        for (int idx = t; idx < 64 * 64; idx += 512) {
            int row = idx >> 6, col = idx & 63;
            sWST[row * 68 + col] = whh[(r * 64 + row) * 64 + col];
        }
        __syncthreads();
        if ((p >> 6) == r) {
            const u64* wr = (const u64*)(sWST + (p & 63) * 68 + hh * 32);
#pragma unroll
            for (int k = 0; k < 16; k++) wpk[k] = wr[k];
        }
        __syncthreads();
    }
    const float* wih = dir ? P.l1b_wih : P.l1f_wih;
    float wi0 = 0.f, wi1 = 0.f, wi2 = 0.f, wi3 = 0.f, bias = 0.f;
    if (hh == 0) {
        wi0 = wih[p * 7 + 0]; wi1 = wih[p * 7 + 1]; wi2 = wih[p * 7 + 2]; wi3 = wih[p * 7 + 3];
        bias = dir ? (P.l1b_bih[p] + P.l1b_bhh[p]) : (P.l1f_bih[p] + P.l1f_bhh[p]);
    } else {
        wi0 = wih[p * 7 + 4]; wi1 = wih[p * 7 + 5]; wi2 = wih[p * 7 + 6];
    }
    if (t < Hn) sH[t] = 0.0f;
    float c1 = 0.0f;
    __syncthreads();

    float* lo = (dir ? g_lob : g_lof) + (size_t)b * (Sn * Hn);

#pragma unroll 1
    for (int step = 0; step < Sn; step++) {
        int s = dir ? (Sn - 1 - step) : step;
        u64 a0 = 0ull, a1 = 0ull;
        const float4* h4 = (const float4*)(sH + (hh << 5));
#pragma unroll
        for (int j = 0; j < 8; j++) {
            float4 hv = h4[j];
            a0 = ffma2(pack2(hv.x, hv.y), wpk[2 * j + 0], a0);
            a1 = ffma2(pack2(hv.z, hv.w), wpk[2 * j + 1], a1);
        }
        float2 f0 = unpack2(a0), f1 = unpack2(a1);
        float a = (f0.x + f0.y) + (f1.x + f1.y);
        const float* fr = sFA + s * 8;
        if (hh == 0) a += bias + fr[0] * wi0 + fr[1] * wi1 + fr[2] * wi2 + fr[3] * wi3;
        else         a += fr[4] * wi0 + fr[5] * wi1 + fr[6] * wi2;
        a += __shfl_xor_sync(0xffffffffu, a, 1);
        if (hh == 0) sG[p] = a;
        __syncthreads();
        if (t < Hn) {
            float gi = sG[t], gf = sG[64 + t], gc = sG[128 + t], go = sG[192 + t];
            c1 = sigf(gf) * c1 + sigf(gi) * tanhfast(gc);
            float h = sigf(go) * tanhfast(c1);
            sH[t] = h;
            lo[s * Hn + t] = 0.5f * h;
        }
        __syncthreads();
    }
}

// =========================== K3: temporal attention + LSTM2-input GEMM ===========================
struct P3 {
    const float *tv_w, *tv_b, *tk_w, *tk_b, *tq_w, *tq_b;
    const float *l2_wih, *l2_bih, *l2_bhh;
};

namespace {
constexpr int K3_LO   = 0;       // 96 x 64  (lo ; later "to")
constexpr int K3_TV   = 6144;    // 96 x 68
constexpr int K3_TK   = 12672;   // 96 x 68
constexpr int K3_TQ   = 19200;   // 96 x 68
constexpr int K3_TATT = 25728;   // 96 x 96
constexpr int K3_WST  = 34944;   // 64 x 68
constexpr int K3_FLOATS = 39296; // 157184 bytes
}

__global__ void __launch_bounds__(512, 1) k3_tempatt(P3 P) {
    extern __shared__ float sm[];
    const int b = blockIdx.x, t = threadIdx.x;

    {
        const float* lf = g_lof + (size_t)b * (Sn * Hn);
        const float* lb = g_lob + (size_t)b * (Sn * Hn);
        for (int idx = t; idx < Sn * Hn; idx += 512) sm[K3_LO + idx] = lf[idx] + lb[idx];
    }
    __syncthreads();

    // tv/tk/tq = lo @ W^T + b
    {
        const float* Ws[3] = { P.tv_w, P.tk_w, P.tq_w };
        const float* Bs[3] = { P.tv_b, P.tk_b, P.tq_b };
        const int outs[3] = { K3_TV, K3_TK, K3_TQ };
#pragma unroll 1
        for (int m = 0; m < 3; m++) {
            for (int idx = t; idx < 64 * 64; idx += 512) {
                int row = idx >> 6, col = idx & 63;
                sm[K3_WST + row * 68 + col] = Ws[m][idx];
            }
            __syncthreads();
            {
                int i = t & 63, sb = t >> 6;
                u64 wpk[32];
                const u64* wr = (const u64*)(sm + K3_WST + i * 68);
#pragma unroll
                for (int k = 0; k < 32; k++) wpk[k] = wr[k];
                float bi = Bs[m][i];
                for (int s12 = 0; s12 < 12; s12++) {
                    int s = sb * 12 + s12;
                    sm[outs[m] + s * 68 + i] = bi + dot64_pk(sm + K3_LO + s * 64, wpk);
                }
            }
            __syncthreads();
        }
    }

    // tatt[i,j] = tq[i,:].tk[j,:]
#pragma unroll 1
    for (int r = 0; r < 18; r++) {
        int idx = r * 512 + t;
        int i = idx / 96, j = idx - i * 96;
        u64 a0 = 0ull, a1 = 0ull;
        const float4* q4 = (const float4*)(sm + K3_TQ + i * 68);
        const float4* k4 = (const float4*)(sm + K3_TK + j * 68);
#pragma unroll
        for (int d4 = 0; d4 < 16; d4 += 2) {
            float4 qa = q4[d4], ka = k4[d4];
            float4 qb = q4[d4 + 1], kb = k4[d4 + 1];
            a0 = ffma2(pack2(qa.x, qa.y), pack2(ka.x, ka.y), a0);
            a1 = ffma2(pack2(qa.z, qa.w), pack2(ka.z, ka.w), a1);
            a0 = ffma2(pack2(qb.x, qb.y), pack2(kb.x, kb.y), a0);
            a1 = ffma2(pack2(qb.z, qb.w), pack2(kb.z, kb.w), a1);
        }
        float2 f0 = unpack2(a0), f1 = unpack2(a1);
        sm[K3_TATT + idx] = (f0.x + f0.y) + (f1.x + f1.y);
    }
    __syncthreads();

    // softmax rows
    {
        int w = t >> 5, lane = t & 31;
        for (int rr = 0; rr < 6; rr++) {
            int i = w * 6 + rr;
            float* row = sm + K3_TATT + i * 96;
            float v0 = row[lane], v1 = row[lane + 32], v2 = row[lane + 64];
            float m = fmaxf(v0, fmaxf(v1, v2));
#pragma unroll
            for (int off = 16; off > 0; off >>= 1) m = fmaxf(m, __shfl_xor_sync(0xffffffffu, m, off));
            float e0 = __expf(v0 - m), e1 = __expf(v1 - m), e2 = __expf(v2 - m);
            float ssum = e0 + e1 + e2;
#pragma unroll
            for (int off = 16; off > 0; off >>= 1) ssum += __shfl_xor_sync(0xffffffffu, ssum, off);
            float inv = 1.0f / ssum;
            row[lane] = e0 * inv; row[lane + 32] = e1 * inv; row[lane + 64] = e2 * inv;
        }
    }
    __syncthreads();

    // to[i,:] = tanh(tatt[i,:] @ tv)  -> into K3_LO (lo dead)
    {
        int dp = t & 31, ib = t >> 5;
        for (int i6 = 0; i6 < 6; i6++) {
            int i = ib * 6 + i6;
            const float* tar = sm + K3_TATT + i * 96;
            u64 a0 = 0ull, a1 = 0ull;
#pragma unroll
            for (int j = 0; j < 96; j += 2) {
                u64 tv0 = *(const u64*)(sm + K3_TV + j * 68 + 2 * dp);
                u64 tv1 = *(const u64*)(sm + K3_TV + (j + 1) * 68 + 2 * dp);
                a0 = ffma2(dup2(tar[j]), tv0, a0);
                a1 = ffma2(dup2(tar[j + 1]), tv1, a1);
            }
            float2 f0 = unpack2(a0), f1 = unpack2(a1);
            sm[K3_LO + i * 64 + 2 * dp + 0] = tanhfast(f0.x + f1.x);
            sm[K3_LO + i * 64 + 2 * dp + 1] = tanhfast(f0.y + f1.y);
        }
    }
    __syncthreads();

    // xg2[s,g] = to[s] . l2_wih[g] + bih[g] + bhh[g]  -> gmem
    for (int idx = t; idx < 64 * 64; idx += 512) {
        int row = idx >> 6, col = idx & 63;
        sm[K3_WST + row * 68 + col] = P.l2_wih[idx];
    }
    __syncthreads();
    {
        int g2 = t & 63, sb = t >> 6;
        u64 wpk[32];
        const u64* wr = (const u64*)(sm + K3_WST + g2 * 68);
#pragma unroll
        for (int k = 0; k < 32; k++) wpk[k] = wr[k];
        float bi = P.l2_bih[g2] + P.l2_bhh[g2];
        float* xgp = g_xg + (size_t)b * (Sn * Hn);
        for (int s12 = 0; s12 < 12; s12++) {
            int s = sb * 12 + s12;
            xgp[s * 64 + g2] = bi + dot64_pk(sm + K3_LO + s * 64, wpk);
        }
    }
}

// =========================== K4: LSTM2 recurrence + FC, warp-per-batch ===========================
struct P4 { const float *l2_whh, *fc_w, *fc_b; float* out; };

__global__ void __launch_bounds__(256) k4_rec(P4 P) {
    const int warp = blockIdx.x * 8 + (threadIdx.x >> 5);  // batch element
    const int lane = threadIdx.x & 31;
    const float* xg = g_xg + (size_t)warp * (Sn * Hn);
    float* outp = P.out + (size_t)warp * (Sn * Dn);

    // whh rows for gates lane and lane+32 (16 floats each)
    u64 w0[8], w1[8];
    {
        const u64* r0 = (const u64*)(P.l2_whh + lane * 16);
        const u64* r1 = (const u64*)(P.l2_whh + (lane + 32) * 16);
#pragma unroll
        for (int k = 0; k < 8; k++) { w0[k] = r0[k]; w1[k] = r1[k]; }
    }
    // fc row for output feature = lane (lanes 0..6)
    u64 wfc[8]; float fcb;
    {
        int fl = lane < 7 ? lane : 0;
        const u64* rf = (const u64*)(P.fc_w + fl * 16);
#pragma unroll
        for (int k = 0; k < 8; k++) wfc[k] = rf[k];
        fcb = P.fc_b[fl];
    }

    float h = 0.0f, c = 0.0f;          // state for unit (lane & 15)
    float xg0 = xg[lane], xg1 = xg[32 + lane];

#pragma unroll 1
    for (int s = 0; s < Sn; s++) {
        // broadcast h (= h_{s-1}); feeds both the Whh dot and FC of step s-1
        u64 acc0 = 0ull, acc1 = 0ull, accf = 0ull;
#pragma unroll
        for (int m = 0; m < 8; m++) {
            float ha = __shfl_sync(0xffffffffu, h, 2 * m);
            float hb = __shfl_sync(0xffffffffu, h, 2 * m + 1);
            u64 hp = pack2(ha, hb);
            acc0 = ffma2(hp, w0[m], acc0);
            acc1 = ffma2(hp, w1[m], acc1);
            accf = ffma2(hp, wfc[m], accf);
        }
        if (s > 0 && lane < 7) {
            float2 ff = unpack2(accf);
            outp[(s - 1) * 7 + lane] = fcb + ff.x + ff.y;
        }
        float2 f0 = unpack2(acc0), f1 = unpack2(acc1);
        float a0 = xg0 + f0.x + f0.y;
        float a1 = xg1 + f1.x + f1.y;
        if (s + 1 < Sn) {   // prefetch next step's gate inputs
            xg0 = xg[(s + 1) * 64 + lane];
            xg1 = xg[(s + 1) * 64 + 32 + lane];
        }
        // gate exchange: unit j = lane & 15; i=g[j], f=g[16+j], g=g[32+j], o=g[48+j]
        int j = lane & 15;
        float iv = __shfl_sync(0xffffffffu, a0, j);
        float fv = __shfl_sync(0xffffffffu, a0, j + 16);
        float gv = __shfl_sync(0xffffffffu, a1, j);
        float ov = __shfl_sync(0xffffffffu, a1, j + 16);
        c = sigf(fv) * c + sigf(iv) * tanhfast(gv);
        h = sigf(ov) * tanhfast(c);
    }
    // final FC for s = 95
    {
        u64 accf = 0ull;
#pragma unroll
        for (int m = 0; m < 8; m++) {
            float ha = __shfl_sync(0xffffffffu, h, 2 * m);
            float hb = __shfl_sync(0xffffffffu, h, 2 * m + 1);
            accf = ffma2(pack2(ha, hb), wfc[m], accf);
        }
        if (lane < 7) {
            float2 ff = unpack2(accf);
            outp[95 * 7 + lane] = fcb + ff.x + ff.y;
        }
    }
}

// =========================== launch ===========================
extern "C" void kernel_launch(void* const* d_in, const int* in_sizes, int n_in,
                              void* d_out, int out_size) {
    P1 p1; P2 p2; P3 p3; P4 p4;
    p1.x       = (const float*)d_in[0];
    p1.fv_w    = (const float*)d_in[1];  p1.fv_b = (const float*)d_in[2];
    p1.fk_w    = (const float*)d_in[3];  p1.fk_b = (const float*)d_in[4];
    p1.fq_w    = (const float*)d_in[5];  p1.fq_b = (const float*)d_in[6];
    p2.l1f_wih = (const float*)d_in[7];  p2.l1f_whh = (const float*)d_in[8];
    p2.l1f_bih = (const float*)d_in[9];  p2.l1f_bhh = (const float*)d_in[10];
    p2.l1b_wih = (const float*)d_in[11]; p2.l1b_whh = (const float*)d_in[12];
    p2.l1b_bih = (const float*)d_in[13]; p2.l1b_bhh = (const float*)d_in[14];
    p3.tv_w    = (const float*)d_in[15]; p3.tv_b = (const float*)d_in[16];
    p3.tk_w    = (const float*)d_in[17]; p3.tk_b = (const float*)d_in[18];
    p3.tq_w    = (const float*)d_in[19]; p3.tq_b = (const float*)d_in[20];
    p3.l2_wih  = (const float*)d_in[21];
    p3.l2_bih  = (const float*)d_in[23]; p3.l2_bhh = (const float*)d_in[24];
    p4.l2_whh  = (const float*)d_in[22];
    p4.fc_w    = (const float*)d_in[25]; p4.fc_b = (const float*)d_in[26];
    p4.out     = (float*)d_out;

    cudaFuncSetAttribute(k3_tempatt, cudaFuncAttributeMaxDynamicSharedMemorySize,
                         K3_FLOATS * (int)sizeof(float));

    k1_featatt<<<Bn, 128>>>(p1);
    k2_bilstm<<<dim3(Bn, 2), 512>>>(p2);
    k3_tempatt<<<Bn, 512, K3_FLOATS * sizeof(float)>>>(p3);
    k4_rec<<<Bn / 8, 256>>>(p4);
}

// round 5
// speedup vs baseline: 1.5098x; 1.5098x over previous
#include <cuda_runtime.h>

// ---------------------------------------------------------------------------
// ftat_BiLSTM — round 5:
//  K1 feature attention   (2048 x 128t)                 -> g_fa
//  K2 BiLSTM H=64, 4 jobs/CTA (grid (512,2) x 256t)     -> g_lof/g_lob
//  K3 temporal attn + LSTM2-input GEMM (2048 x 512t)    -> g_xg
//  K4 LSTM2 recurrence + FC, warp-per-batch (barrierless)-> out
// ---------------------------------------------------------------------------

namespace {
constexpr int Bn = 2048, Sn = 96, Dn = 7, Hn = 64;
constexpr int NJ = 4;   // jobs (batch elements) per K2 CTA
using u64 = unsigned long long;
} // namespace

__device__ float g_fa [Bn * Sn * 8];    // fa, padded stride 8
__device__ float g_lof[Bn * Sn * Hn];   // 0.5*hf
__device__ float g_lob[Bn * Sn * Hn];   // 0.5*hb
__device__ float g_xg [Bn * Sn * Hn];   // LSTM2 input gates (pre-activation)

__device__ __forceinline__ float sigf(float x) { return 1.0f / (1.0f + __expf(-x)); }
__device__ __forceinline__ float tanhfast(float x) { return 1.0f - 2.0f / (__expf(2.0f * x) + 1.0f); }

__device__ __forceinline__ u64 ffma2(u64 a, u64 b, u64 c) {
    u64 d; asm("fma.rn.f32x2 %0, %1, %2, %3;" : "=l"(d) : "l"(a), "l"(b), "l"(c)); return d;
}
__device__ __forceinline__ float2 unpack2(u64 v) {
    float2 r; asm("mov.b64 {%0, %1}, %2;" : "=f"(r.x), "=f"(r.y) : "l"(v)); return r;
}
__device__ __forceinline__ u64 pack2(float lo, float hi) {
    u64 v; asm("mov.b64 %0, {%1, %2};" : "=l"(v) : "f"(lo), "f"(hi)); return v;
}
__device__ __forceinline__ u64 dup2(float x) {
    u64 v; asm("mov.b64 %0, {%1, %1};" : "=l"(v) : "f"(x)); return v;
}

// packed dot over 64 floats: x via float4 loads, w as 32 packed u64.
// u64 w[k] covers floats (2k, 2k+1); float4 x4[j] pairs with w[2j], w[2j+1].
__device__ __forceinline__ float dot64_pk(const float* __restrict__ x, const u64* __restrict__ w) {
    u64 a0 = 0ull, a1 = 0ull, a2 = 0ull, a3 = 0ull;
    const float4* x4 = (const float4*)x;
#pragma unroll
    for (int j = 0; j < 16; j += 2) {
        float4 v0 = x4[j], v1 = x4[j + 1];
        a0 = ffma2(pack2(v0.x, v0.y), w[2 * j + 0], a0);
        a1 = ffma2(pack2(v0.z, v0.w), w[2 * j + 1], a1);
        a2 = ffma2(pack2(v1.x, v1.y), w[2 * j + 2], a2);
        a3 = ffma2(pack2(v1.z, v1.w), w[2 * j + 3], a3);
    }
    float2 f0 = unpack2(a0), f1 = unpack2(a1), f2 = unpack2(a2), f3 = unpack2(a3);
    return ((f0.x + f0.y) + (f1.x + f1.y)) + ((f2.x + f2.y) + (f3.x + f3.y));
}

// =========================== K1: feature attention ===========================
struct P1 { const float *x, *fv_w, *fv_b, *fk_w, *fk_b, *fq_w, *fq_b; };

__global__ void __launch_bounds__(128) k1_featatt(P1 P) {
    __shared__ __align__(16) float sFA[Sn * 8];
    __shared__ __align__(16) float sV[Sn * 8];
    __shared__ __align__(16) float sK[Sn * 8];
    __shared__ __align__(16) float sQ[Sn * 8];
    __shared__ float sATT[7 * 8];
    const int b = blockIdx.x, t = threadIdx.x;
    const float* x = P.x + (size_t)b * (Sn * Dn);
    for (int idx = t; idx < Sn * Dn; idx += 128) {
        int s = idx / 7, j = idx - s * 7;
        sFA[s * 8 + j] = x[idx];
    }
    if (t < Sn) sFA[t * 8 + 7] = 0.0f;
    __syncthreads();
    for (int idx = t; idx < Sn * Dn; idx += 128) {
        int s = idx / 7, i = idx - s * 7;
        float a = P.fv_b[i];
#pragma unroll
        for (int j = 0; j < 7; j++) a += sFA[s * 8 + j] * P.fv_w[i * 7 + j];
        sV[s * 8 + i] = a;
    }
    __syncthreads();
    for (int idx = t; idx < Sn * Dn; idx += 128) {
        int s = idx / 7, i = idx - s * 7;
        float a = P.fk_b[i];
#pragma unroll
        for (int j = 0; j < 7; j++) a += (sFA[s * 8 + j] + sV[s * 8 + j]) * P.fk_w[i * 7 + j];
        sK[s * 8 + i] = a;
    }
    __syncthreads();
    for (int idx = t; idx < Sn * Dn; idx += 128) {
        int s = idx / 7, i = idx - s * 7;
        float a = P.fq_b[i];
#pragma unroll
        for (int j = 0; j < 7; j++) a += (sFA[s * 8 + j] + sK[s * 8 + j]) * P.fq_w[i * 7 + j];
        sQ[s * 8 + i] = a;
    }
    __syncthreads();
    if (t < 49) {
        int i = t / 7, j = t - (t / 7) * 7;
        float a = 0.0f;
        for (int s = 0; s < Sn; s++) a += sQ[s * 8 + i] * sK[s * 8 + j];
        sATT[i * 8 + j] = a;
    }
    __syncthreads();
    if (t < 7) {
        float* row = sATT + t * 8;
        float m = row[0];
#pragma unroll
        for (int j = 1; j < 7; j++) m = fmaxf(m, row[j]);
        float ssum = 0.0f;
#pragma unroll
        for (int j = 0; j < 7; j++) { float e = __expf(row[j] - m); row[j] = e; ssum += e; }
        float inv = 1.0f / ssum;
#pragma unroll
        for (int j = 0; j < 7; j++) row[j] *= inv;
    }
    __syncthreads();
    for (int idx = t; idx < Sn * Dn; idx += 128) {
        int s = idx / 7, j = idx - s * 7;
        float a = sFA[s * 8 + j];
#pragma unroll
        for (int i = 0; i < 7; i++) a += sV[s * 8 + i] * sATT[i * 8 + j];
        sFA[s * 8 + j] = tanhfast(a);
    }
    __syncthreads();
    float* fa = g_fa + (size_t)b * (Sn * 8);
    for (int idx = t; idx < Sn * 8; idx += 128) fa[idx] = sFA[idx];
}

// =========================== K2: BiLSTM, 4 jobs per CTA ===========================
struct P2 {
    const float *l1f_wih, *l1f_whh, *l1f_bih, *l1f_bhh;
    const float *l1b_wih, *l1b_whh, *l1b_bih, *l1b_bhh;
};

__global__ void __launch_bounds__(256, 2) k2_bilstm(P2 P) {
    __shared__ __align__(16) float sFA[NJ][Sn * 8];   // 12 KB
    __shared__ __align__(16) float sWST[64 * 68];     // 17.4 KB (staging)
    __shared__ __align__(16) float sH[NJ][Hn];        // 1 KB
    __shared__ float sG[NJ][256];                     // 4 KB
    const int bx = blockIdx.x, dir = blockIdx.y, t = threadIdx.x;  // t = gate 0..255

    // load fa for 4 jobs
    for (int idx = t; idx < NJ * Sn * 8; idx += 256) {
        int jj = idx / (Sn * 8), r = idx - jj * (Sn * 8);
        sFA[jj][r] = g_fa[(size_t)(NJ * bx + jj) * (Sn * 8) + r];
    }
    // stage Whh (256x64) in 4 rounds of 64 rows; thread t grabs row t
    const float* whh = dir ? P.l1b_whh : P.l1f_whh;
    u64 wpk[32];
#pragma unroll 1
    for (int r = 0; r < 4; r++) {
        for (int idx = t; idx < 64 * 64; idx += 256) {
            int row = idx >> 6, col = idx & 63;
            sWST[row * 68 + col] = whh[(r * 64 + row) * 64 + col];
        }
        __syncthreads();
        if ((t >> 6) == r) {
            const u64* wr = (const u64*)(sWST + (t & 63) * 68);
#pragma unroll
            for (int k = 0; k < 32; k++) wpk[k] = wr[k];
        }
        __syncthreads();
    }
    float wi[7], bias;
    {
        const float* wih = dir ? P.l1b_wih : P.l1f_wih;
#pragma unroll
        for (int j = 0; j < 7; j++) wi[j] = wih[t * 7 + j];
        bias = dir ? (P.l1b_bih[t] + P.l1b_bhh[t]) : (P.l1f_bih[t] + P.l1f_bhh[t]);
    }
    // activation assignment: thread t -> (job jjA, unit uA); 256 = 4 x 64 exactly
    const int jjA = t >> 6, uA = t & 63;
    ((float*)sH)[t] = 0.0f;
    float c1 = 0.0f;
    __syncthreads();

    float* loA = (dir ? g_lob : g_lof) + (size_t)(NJ * bx + jjA) * (Sn * Hn);

#pragma unroll 1
    for (int step = 0; step < Sn; step++) {
        const int s = dir ? (Sn - 1 - step) : step;
        // 4 gate-dots (one per job) — independent chains for ILP
#pragma unroll
        for (int jj = 0; jj < NJ; jj++) {
            u64 a0 = 0ull, a1 = 0ull, a2 = 0ull, a3 = 0ull;
            const float4* h4 = (const float4*)sH[jj];
#pragma unroll
            for (int q = 0; q < 16; q += 2) {
                float4 v0 = h4[q], v1 = h4[q + 1];
                a0 = ffma2(pack2(v0.x, v0.y), wpk[2 * q + 0], a0);
                a1 = ffma2(pack2(v0.z, v0.w), wpk[2 * q + 1], a1);
                a2 = ffma2(pack2(v1.x, v1.y), wpk[2 * q + 2], a2);
                a3 = ffma2(pack2(v1.z, v1.w), wpk[2 * q + 3], a3);
            }
            float2 f0 = unpack2(a0), f1 = unpack2(a1), f2 = unpack2(a2), f3 = unpack2(a3);
            float a = bias + ((f0.x + f0.y) + (f1.x + f1.y)) + ((f2.x + f2.y) + (f3.x + f3.y));
            const float* fr = sFA[jj] + s * 8;
#pragma unroll
            for (int j = 0; j < 7; j++) a += fr[j] * wi[j];
            sG[jj][t] = a;
        }
        __syncthreads();
        // activation: all 256 threads, one (job, unit) each
        {
            float gi = sG[jjA][uA], gf = sG[jjA][64 + uA];
            float gc = sG[jjA][128 + uA], go = sG[jjA][192 + uA];
            c1 = sigf(gf) * c1 + sigf(gi) * tanhfast(gc);
            float h = sigf(go) * tanhfast(c1);
            sH[jjA][uA] = h;
            loA[s * Hn + uA] = 0.5f * h;
        }
        __syncthreads();
    }
}

// =========================== K3: temporal attention + LSTM2-input GEMM ===========================
struct P3 {
    const float *tv_w, *tv_b, *tk_w, *tk_b, *tq_w, *tq_b;
    const float *l2_wih, *l2_bih, *l2_bhh;
};

namespace {
constexpr int K3_LO   = 0;       // 96 x 64  (lo ; later "to")
constexpr int K3_TV   = 6144;    // 96 x 68
constexpr int K3_TK   = 12672;   // 96 x 68
constexpr int K3_TQ   = 19200;   // 96 x 68
constexpr int K3_TATT = 25728;   // 96 x 96
constexpr int K3_WST  = 34944;   // 64 x 68
constexpr int K3_FLOATS = 39296; // 157184 bytes
}

__global__ void __launch_bounds__(512, 1) k3_tempatt(P3 P) {
    extern __shared__ float sm[];
    const int b = blockIdx.x, t = threadIdx.x;

    {
        const float* lf = g_lof + (size_t)b * (Sn * Hn);
        const float* lb = g_lob + (size_t)b * (Sn * Hn);
        for (int idx = t; idx < Sn * Hn; idx += 512) sm[K3_LO + idx] = lf[idx] + lb[idx];
    }
    __syncthreads();

    // tv/tk/tq = lo @ W^T + b
    {
        const float* Ws[3] = { P.tv_w, P.tk_w, P.tq_w };
        const float* Bs[3] = { P.tv_b, P.tk_b, P.tq_b };
        const int outs[3] = { K3_TV, K3_TK, K3_TQ };
#pragma unroll 1
        for (int m = 0; m < 3; m++) {
            for (int idx = t; idx < 64 * 64; idx += 512) {
                int row = idx >> 6, col = idx & 63;
                sm[K3_WST + row * 68 + col] = Ws[m][idx];
            }
            __syncthreads();
            {
                int i = t & 63, sb = t >> 6;
                u64 wpk[32];
                const u64* wr = (const u64*)(sm + K3_WST + i * 68);
#pragma unroll
                for (int k = 0; k < 32; k++) wpk[k] = wr[k];
                float bi = Bs[m][i];
                for (int s12 = 0; s12 < 12; s12++) {
                    int s = sb * 12 + s12;
                    sm[outs[m] + s * 68 + i] = bi + dot64_pk(sm + K3_LO + s * 64, wpk);
                }
            }
            __syncthreads();
        }
    }

    // tatt[i,j] = tq[i,:].tk[j,:]
#pragma unroll 1
    for (int r = 0; r < 18; r++) {
        int idx = r * 512 + t;
        int i = idx / 96, j = idx - i * 96;
        u64 a0 = 0ull, a1 = 0ull;
        const float4* q4 = (const float4*)(sm + K3_TQ + i * 68);
        const float4* k4 = (const float4*)(sm + K3_TK + j * 68);
#pragma unroll
        for (int d4 = 0; d4 < 16; d4 += 2) {
            float4 qa = q4[d4], ka = k4[d4];
            float4 qb = q4[d4 + 1], kb = k4[d4 + 1];
            a0 = ffma2(pack2(qa.x, qa.y), pack2(ka.x, ka.y), a0);
            a1 = ffma2(pack2(qa.z, qa.w), pack2(ka.z, ka.w), a1);
            a0 = ffma2(pack2(qb.x, qb.y), pack2(kb.x, kb.y), a0);
            a1 = ffma2(pack2(qb.z, qb.w), pack2(kb.z, kb.w), a1);
        }
        float2 f0 = unpack2(a0), f1 = unpack2(a1);
        sm[K3_TATT + idx] = (f0.x + f0.y) + (f1.x + f1.y);
    }
    __syncthreads();

    // softmax rows
    {
        int w = t >> 5, lane = t & 31;
        for (int rr = 0; rr < 6; rr++) {
            int i = w * 6 + rr;
            float* row = sm + K3_TATT + i * 96;
            float v0 = row[lane], v1 = row[lane + 32], v2 = row[lane + 64];
            float m = fmaxf(v0, fmaxf(v1, v2));
#pragma unroll
            for (int off = 16; off > 0; off >>= 1) m = fmaxf(m, __shfl_xor_sync(0xffffffffu, m, off));
            float e0 = __expf(v0 - m), e1 = __expf(v1 - m), e2 = __expf(v2 - m);
            float ssum = e0 + e1 + e2;
#pragma unroll
            for (int off = 16; off > 0; off >>= 1) ssum += __shfl_xor_sync(0xffffffffu, ssum, off);
            float inv = 1.0f / ssum;
            row[lane] = e0 * inv; row[lane + 32] = e1 * inv; row[lane + 64] = e2 * inv;
        }
    }
    __syncthreads();

    // to[i,:] = tanh(tatt[i,:] @ tv)  -> into K3_LO (lo dead)
    {
        int dp = t & 31, ib = t >> 5;
        for (int i6 = 0; i6 < 6; i6++) {
            int i = ib * 6 + i6;
            const float* tar = sm + K3_TATT + i * 96;
            u64 a0 = 0ull, a1 = 0ull;
#pragma unroll
            for (int j = 0; j < 96; j += 2) {
                u64 tv0 = *(const u64*)(sm + K3_TV + j * 68 + 2 * dp);
                u64 tv1 = *(const u64*)(sm + K3_TV + (j + 1) * 68 + 2 * dp);
                a0 = ffma2(dup2(tar[j]), tv0, a0);
                a1 = ffma2(dup2(tar[j + 1]), tv1, a1);
            }
            float2 f0 = unpack2(a0), f1 = unpack2(a1);
            sm[K3_LO + i * 64 + 2 * dp + 0] = tanhfast(f0.x + f1.x);
            sm[K3_LO + i * 64 + 2 * dp + 1] = tanhfast(f0.y + f1.y);
        }
    }
    __syncthreads();

    // xg2[s,g] = to[s] . l2_wih[g] + bih[g] + bhh[g]  -> gmem
    for (int idx = t; idx < 64 * 64; idx += 512) {
        int row = idx >> 6, col = idx & 63;
        sm[K3_WST + row * 68 + col] = P.l2_wih[idx];
    }
    __syncthreads();
    {
        int g2 = t & 63, sb = t >> 6;
        u64 wpk[32];
        const u64* wr = (const u64*)(sm + K3_WST + g2 * 68);
#pragma unroll
        for (int k = 0; k < 32; k++) wpk[k] = wr[k];
        float bi = P.l2_bih[g2] + P.l2_bhh[g2];
        float* xgp = g_xg + (size_t)b * (Sn * Hn);
        for (int s12 = 0; s12 < 12; s12++) {
            int s = sb * 12 + s12;
            xgp[s * 64 + g2] = bi + dot64_pk(sm + K3_LO + s * 64, wpk);
        }
    }
}

// =========================== K4: LSTM2 recurrence + FC, warp-per-batch ===========================
struct P4 { const float *l2_whh, *fc_w, *fc_b; float* out; };

__global__ void __launch_bounds__(256) k4_rec(P4 P) {
    const int warp = blockIdx.x * 8 + (threadIdx.x >> 5);  // batch element
    const int lane = threadIdx.x & 31;
    const float* xg = g_xg + (size_t)warp * (Sn * Hn);
    float* outp = P.out + (size_t)warp * (Sn * Dn);

    // whh rows for gates lane and lane+32 (16 floats each)
    u64 w0[8], w1[8];
    {
        const u64* r0 = (const u64*)(P.l2_whh + lane * 16);
        const u64* r1 = (const u64*)(P.l2_whh + (lane + 32) * 16);
#pragma unroll
        for (int k = 0; k < 8; k++) { w0[k] = r0[k]; w1[k] = r1[k]; }
    }
    // fc row for output feature = lane (lanes 0..6)
    u64 wfc[8]; float fcb;
    {
        int fl = lane < 7 ? lane : 0;
        const u64* rf = (const u64*)(P.fc_w + fl * 16);
#pragma unroll
        for (int k = 0; k < 8; k++) wfc[k] = rf[k];
        fcb = P.fc_b[fl];
    }

    float h = 0.0f, c = 0.0f;          // state for unit (lane & 15)
    float xg0 = xg[lane], xg1 = xg[32 + lane];

#pragma unroll 1
    for (int s = 0; s < Sn; s++) {
        // broadcast h (= h_{s-1}); feeds both the Whh dot and FC of step s-1
        u64 acc0 = 0ull, acc1 = 0ull, accf = 0ull;
#pragma unroll
        for (int m = 0; m < 8; m++) {
            float ha = __shfl_sync(0xffffffffu, h, 2 * m);
            float hb = __shfl_sync(0xffffffffu, h, 2 * m + 1);
            u64 hp = pack2(ha, hb);
            acc0 = ffma2(hp, w0[m], acc0);
            acc1 = ffma2(hp, w1[m], acc1);
            accf = ffma2(hp, wfc[m], accf);
        }
        if (s > 0 && lane < 7) {
            float2 ff = unpack2(accf);
            outp[(s - 1) * 7 + lane] = fcb + ff.x + ff.y;
        }
        float2 f0 = unpack2(acc0), f1 = unpack2(acc1);
        float a0 = xg0 + f0.x + f0.y;
        float a1 = xg1 + f1.x + f1.y;
        if (s + 1 < Sn) {   // prefetch next step's gate inputs
            xg0 = xg[(s + 1) * 64 + lane];
            xg1 = xg[(s + 1) * 64 + 32 + lane];
        }
        // gate exchange: unit j = lane & 15; i=g[j], f=g[16+j], g=g[32+j], o=g[48+j]
        int j = lane & 15;
        float iv = __shfl_sync(0xffffffffu, a0, j);
        float fv = __shfl_sync(0xffffffffu, a0, j + 16);
        float gv = __shfl_sync(0xffffffffu, a1, j);
        float ov = __shfl_sync(0xffffffffu, a1, j + 16);
        c = sigf(fv) * c + sigf(iv) * tanhfast(gv);
        h = sigf(ov) * tanhfast(c);
    }
    // final FC for s = 95
    {
        u64 accf = 0ull;
#pragma unroll
        for (int m = 0; m < 8; m++) {
            float ha = __shfl_sync(0xffffffffu, h, 2 * m);
            float hb = __shfl_sync(0xffffffffu, h, 2 * m + 1);
            accf = ffma2(pack2(ha, hb), wfc[m], accf);
        }
        if (lane < 7) {
            float2 ff = unpack2(accf);
            outp[95 * 7 + lane] = fcb + ff.x + ff.y;
        }
    }
}

// =========================== launch ===========================
extern "C" void kernel_launch(void* const* d_in, const int* in_sizes, int n_in,
                              void* d_out, int out_size) {
    P1 p1; P2 p2; P3 p3; P4 p4;
    p1.x       = (const float*)d_in[0];
    p1.fv_w    = (const float*)d_in[1];  p1.fv_b = (const float*)d_in[2];
    p1.fk_w    = (const float*)d_in[3];  p1.fk_b = (const float*)d_in[4];
    p1.fq_w    = (const float*)d_in[5];  p1.fq_b = (const float*)d_in[6];
    p2.l1f_wih = (const float*)d_in[7];  p2.l1f_whh = (const float*)d_in[8];
    p2.l1f_bih = (const float*)d_in[9];  p2.l1f_bhh = (const float*)d_in[10];
    p2.l1b_wih = (const float*)d_in[11]; p2.l1b_whh = (const float*)d_in[12];
    p2.l1b_bih = (const float*)d_in[13]; p2.l1b_bhh = (const float*)d_in[14];
    p3.tv_w    = (const float*)d_in[15]; p3.tv_b = (const float*)d_in[16];
    p3.tk_w    = (const float*)d_in[17]; p3.tk_b = (const float*)d_in[18];
    p3.tq_w    = (const float*)d_in[19]; p3.tq_b = (const float*)d_in[20];
    p3.l2_wih  = (const float*)d_in[21];
    p3.l2_bih  = (const float*)d_in[23]; p3.l2_bhh = (const float*)d_in[24];
    p4.l2_whh  = (const float*)d_in[22];
    p4.fc_w    = (const float*)d_in[25]; p4.fc_b = (const float*)d_in[26];
    p4.out     = (float*)d_out;

    cudaFuncSetAttribute(k3_tempatt, cudaFuncAttributeMaxDynamicSharedMemorySize,
                         K3_FLOATS * (int)sizeof(float));

    k1_featatt<<<Bn, 128>>>(p1);
    k2_bilstm<<<dim3(Bn / NJ, 2), 256>>>(p2);
    k3_tempatt<<<Bn, 512, K3_FLOATS * sizeof(float)>>>(p3);
    k4_rec<<<Bn / 8, 256>>>(p4);
}